// round 2
// baseline (speedup 1.0000x reference)
#include <cuda_runtime.h>
#include <cstdint>

// ---------------------------------------------------------------------------
// ModuleDistLayers: fused graph-NN distance layers + fc, fp32 baseline.
//
// Pipeline (7 launches, all graph-capturable, zero allocations):
//   K0 zero      : clear segment accumulators + BN stats
//   K1 segsum    : read x once; run-length-aggregated atomics for sorted
//                  atom_idx, direct atomics for random ele_idx
//   K2 finalize  : pa = relu(atom_sum/max(cnt,1)), pe likewise
//   K3 layer x2  : h = W @ [feat|pa|pe] + b  (K=192 GEMM, 128x128 CTA tile,
//                  8x8 reg tile) + per-feature sum/sumsq accumulation
//   K4 bnparams  : scale/shift per feature from stats
//   K5 fc        : x1 = relu(h1*s1+t1+x), x2 = relu(h2*s2+t2+x),
//                  out = relu(fcW @ [x1|x2] + fcb)  (K=256 GEMM)
// ---------------------------------------------------------------------------

#define N_GRAPHS 4096
#define N_ELE    16384
#define MAX_N    500000
#define D        128          // 2*n_ae
#define NAE      64

// ---------------- device-global scratch (no allocations allowed) -----------
__device__ float g_atom_sum[N_GRAPHS * NAE];
__device__ float g_atom_cnt[N_GRAPHS];
__device__ float g_ele_sum[N_ELE * NAE];
__device__ float g_ele_cnt[N_ELE];
__device__ float g_pa[N_GRAPHS * NAE];
__device__ float g_pe[N_ELE * NAE];
__device__ float g_h1[(size_t)MAX_N * D];   // 256 MB pre-BN layer-1 output
__device__ float g_h2[(size_t)MAX_N * D];   // 256 MB pre-BN layer-2 output
__device__ float g_stats[4 * D];            // sum1, sq1, sum2, sq2
__device__ float g_bn[4 * D];               // scale1, shift1, scale2, shift2

// ---------------------------------------------------------------------------
// K0: zero accumulators
// ---------------------------------------------------------------------------
__global__ void zero_kernel() {
    int i  = blockIdx.x * blockDim.x + threadIdx.x;
    int gs = gridDim.x * blockDim.x;
    for (int j = i; j < N_GRAPHS * NAE; j += gs) g_atom_sum[j] = 0.f;
    for (int j = i; j < N_ELE * NAE;    j += gs) g_ele_sum[j]  = 0.f;
    for (int j = i; j < N_GRAPHS;       j += gs) g_atom_cnt[j] = 0.f;
    for (int j = i; j < N_ELE;          j += gs) g_ele_cnt[j]  = 0.f;
    for (int j = i; j < 4 * D;          j += gs) g_stats[j]    = 0.f;
}

// ---------------------------------------------------------------------------
// K1: segment sums.  Block = 64 rows; thread (c, sg): column c of a 16-row
// window.  atom_idx is sorted -> run-length aggregation before atomicAdd.
// ---------------------------------------------------------------------------
__global__ void segsum_kernel(const float* __restrict__ x,
                              const int*   __restrict__ aidx,
                              const int*   __restrict__ eidx,
                              int N) {
    int tid = threadIdx.x;            // 256
    int c   = tid & 63;
    int sg  = tid >> 6;               // 0..3
    int r0  = blockIdx.x * 64 + sg * 16;

    int   cur = -1;
    float acc = 0.f;
    float runCnt = 0.f;

    for (int t = 0; t < 16; ++t) {
        int row = r0 + t;
        if (row >= N) break;
        int   a = aidx[row];
        float v = x[(size_t)row * D + c];
        if (a != cur) {
            if (cur >= 0) {
                atomicAdd(&g_atom_sum[cur * NAE + c], acc);
                if (c == 0) atomicAdd(&g_atom_cnt[cur], runCnt);
            }
            cur = a; acc = v; runCnt = 1.f;
        } else {
            acc += v; runCnt += 1.f;
        }
        int e = eidx[row];
        atomicAdd(&g_ele_sum[e * NAE + c], x[(size_t)row * D + NAE + c]);
        if (c == 0) atomicAdd(&g_ele_cnt[e], 1.f);
    }
    if (cur >= 0) {
        atomicAdd(&g_atom_sum[cur * NAE + c], acc);
        if (c == 0) atomicAdd(&g_atom_cnt[cur], runCnt);
    }
}

// ---------------------------------------------------------------------------
// K2: pa = relu(sum / max(cnt,1)), pe likewise
// ---------------------------------------------------------------------------
__global__ void finalize_kernel() {
    int i  = blockIdx.x * blockDim.x + threadIdx.x;
    int gs = gridDim.x * blockDim.x;
    for (int j = i; j < N_GRAPHS * NAE; j += gs) {
        float m = g_atom_sum[j] / fmaxf(g_atom_cnt[j >> 6], 1.f);
        g_pa[j] = fmaxf(m, 0.f);
    }
    for (int j = i; j < N_ELE * NAE; j += gs) {
        float m = g_ele_sum[j] / fmaxf(g_ele_cnt[j >> 6], 1.f);
        g_pe[j] = fmaxf(m, 0.f);
    }
}

// ---------------------------------------------------------------------------
// K3: layer GEMM + stats.  CTA tile: 128 rows x 128 outs, K=192.
// smem: sW [192][128] (transposed weights), sIn [192][132] (transposed input).
// 256 threads, 8x8 register tile each.
// ---------------------------------------------------------------------------
#define LK    192
#define LDI   132                      // padded row stride of sIn (mult of 4)
#define SMEM_LAYER ((LK * D + LK * LDI) * 4)

__global__ __launch_bounds__(256, 1)
void layer_gemm_kernel(const float* __restrict__ feat,   // [N][64]
                       const int*   __restrict__ aidx,
                       const int*   __restrict__ eidx,
                       const float* __restrict__ W,      // [128][192]
                       const float* __restrict__ bias,   // [128]
                       int layer, int N) {
    extern __shared__ float sm[];
    float* sW  = sm;                   // [192][128]
    float* sIn = sm + LK * D;          // [192][LDI]
    __shared__ float sSum[D];
    __shared__ float sSq[D];
    __shared__ int   sA[128];
    __shared__ int   sE[128];

    int tid   = threadIdx.x;
    int rbase = blockIdx.x * 128;

    // ---- load W transposed: thread (o = tid&127, half = tid>>7) ----
    {
        int o = tid & 127, half = tid >> 7;
        const float4* src = (const float4*)(W + (size_t)o * LK) + half * 24;
        #pragma unroll
        for (int j = 0; j < 24; ++j) {
            float4 v = src[j];
            int k = half * 96 + j * 4;
            sW[(k + 0) * D + o] = v.x;
            sW[(k + 1) * D + o] = v.y;
            sW[(k + 2) * D + o] = v.z;
            sW[(k + 3) * D + o] = v.w;
        }
    }
    if (tid < 128) {
        int r = rbase + tid;
        sA[tid] = (r < N) ? aidx[r] : 0;
        sE[tid] = (r < N) ? eidx[r] : 0;
        sSum[tid] = 0.f;
        sSq[tid]  = 0.f;
    }
    __syncthreads();

    // ---- build input tile: [feat | pa | pe] transposed into sIn[k][row] ----
    {
        int c = tid & 63, rr = tid >> 6;
        for (int r = rr; r < 128; r += 4) {
            int row = rbase + r;
            float f = 0.f, pav = 0.f, pev = 0.f;
            if (row < N) {
                f   = feat[(size_t)row * NAE + c];
                pav = g_pa[sA[r] * NAE + c];
                pev = g_pe[sE[r] * NAE + c];
            }
            sIn[c * LDI + r]          = f;
            sIn[(NAE + c) * LDI + r]  = pav;
            sIn[(2*NAE + c) * LDI + r] = pev;
        }
    }
    __syncthreads();

    // ---- GEMM: thread tile 8 rows x 8 outs ----
    int og = tid & 15, rg = tid >> 4;
    int o0 = og * 8, r0 = rg * 8;

    float acc[8][8];
    #pragma unroll
    for (int i = 0; i < 8; ++i)
        #pragma unroll
        for (int j = 0; j < 8; ++j) acc[i][j] = 0.f;

    #pragma unroll 8
    for (int k = 0; k < LK; ++k) {
        float a[8], b[8];
        float4 t;
        t = *(const float4*)(sIn + k * LDI + r0);     a[0]=t.x; a[1]=t.y; a[2]=t.z; a[3]=t.w;
        t = *(const float4*)(sIn + k * LDI + r0 + 4); a[4]=t.x; a[5]=t.y; a[6]=t.z; a[7]=t.w;
        t = *(const float4*)(sW  + k * D   + o0);     b[0]=t.x; b[1]=t.y; b[2]=t.z; b[3]=t.w;
        t = *(const float4*)(sW  + k * D   + o0 + 4); b[4]=t.x; b[5]=t.y; b[6]=t.z; b[7]=t.w;
        #pragma unroll
        for (int i = 0; i < 8; ++i)
            #pragma unroll
            for (int j = 0; j < 8; ++j)
                acc[i][j] = fmaf(a[i], b[j], acc[i][j]);
    }

    // ---- epilogue: +bias, write h, accumulate stats ----
    float* h_out = (layer == 0) ? g_h1 : g_h2;
    float bv[8];
    #pragma unroll
    for (int j = 0; j < 8; ++j) bv[j] = bias[o0 + j];

    float ps[8], pq[8];
    #pragma unroll
    for (int j = 0; j < 8; ++j) { ps[j] = 0.f; pq[j] = 0.f; }

    #pragma unroll
    for (int i = 0; i < 8; ++i) {
        int row = rbase + r0 + i;
        if (row < N) {
            float v[8];
            #pragma unroll
            for (int j = 0; j < 8; ++j) {
                v[j] = acc[i][j] + bv[j];
                ps[j] += v[j];
                pq[j] += v[j] * v[j];
            }
            float4 w0 = make_float4(v[0], v[1], v[2], v[3]);
            float4 w1 = make_float4(v[4], v[5], v[6], v[7]);
            *(float4*)(h_out + (size_t)row * D + o0)     = w0;
            *(float4*)(h_out + (size_t)row * D + o0 + 4) = w1;
        }
    }
    #pragma unroll
    for (int j = 0; j < 8; ++j) {
        atomicAdd(&sSum[o0 + j], ps[j]);
        atomicAdd(&sSq[o0 + j],  pq[j]);
    }
    __syncthreads();
    if (tid < 128) {
        float* ssum = g_stats + layer * (2 * D);
        atomicAdd(&ssum[tid],      sSum[tid]);
        atomicAdd(&ssum[D + tid],  sSq[tid]);
    }
}

// ---------------------------------------------------------------------------
// K4: BN scale/shift per feature
// ---------------------------------------------------------------------------
__global__ void bnparams_kernel(const float* __restrict__ g1, const float* __restrict__ b1,
                                const float* __restrict__ g2, const float* __restrict__ b2,
                                float invN) {
    int o = threadIdx.x;   // 128
    float m  = g_stats[o] * invN;
    float v  = fmaxf(g_stats[D + o] * invN - m * m, 0.f);
    float sc = g1[o] * rsqrtf(v + 1e-5f);
    g_bn[o]       = sc;
    g_bn[D + o]   = b1[o] - m * sc;

    m  = g_stats[2 * D + o] * invN;
    v  = fmaxf(g_stats[3 * D + o] * invN - m * m, 0.f);
    sc = g2[o] * rsqrtf(v + 1e-5f);
    g_bn[2 * D + o] = sc;
    g_bn[3 * D + o] = b2[o] - m * sc;
}

// ---------------------------------------------------------------------------
// K5: BN + residual + relu + fc GEMM.  CTA tile 64 rows x 128 outs, K=256.
// smem: sW [256][128], sIn [256][68].  128 threads, 8x8 reg tile.
// ---------------------------------------------------------------------------
#define FK    256
#define LDI2  68
#define SMEM_FC ((FK * D + FK * LDI2) * 4)

__global__ __launch_bounds__(128, 1)
void fc_gemm_kernel(const float* __restrict__ x,     // [N][128]
                    const float* __restrict__ fcW,   // [128][256]
                    const float* __restrict__ fcb,   // [128]
                    float* __restrict__ out, int N) {
    extern __shared__ float sm[];
    float* sW  = sm;                 // [256][128]
    float* sIn = sm + FK * D;        // [256][LDI2]

    int tid   = threadIdx.x;         // 128
    int rbase = blockIdx.x * 64;

    // ---- load W transposed ----
    {
        int o = tid;
        const float4* src = (const float4*)(fcW + (size_t)o * FK);
        #pragma unroll
        for (int j = 0; j < 64; ++j) {
            float4 v = src[j];
            int k = j * 4;
            sW[(k + 0) * D + o] = v.x;
            sW[(k + 1) * D + o] = v.y;
            sW[(k + 2) * D + o] = v.z;
            sW[(k + 3) * D + o] = v.w;
        }
    }

    // ---- build input tile: x1 rows -> sIn[0..127][r], x2 -> sIn[128..255][r]
    {
        int c = tid;
        float s1 = g_bn[c],         t1 = g_bn[D + c];
        float s2 = g_bn[2 * D + c], t2 = g_bn[3 * D + c];
        for (int r = 0; r < 64; ++r) {
            int row = rbase + r;
            float x1 = 0.f, x2 = 0.f;
            if (row < N) {
                float xv = x[(size_t)row * D + c];
                x1 = fmaxf(fmaf(g_h1[(size_t)row * D + c], s1, t1) + xv, 0.f);
                x2 = fmaxf(fmaf(g_h2[(size_t)row * D + c], s2, t2) + xv, 0.f);
            }
            sIn[c * LDI2 + r]       = x1;
            sIn[(D + c) * LDI2 + r] = x2;
        }
    }
    __syncthreads();

    // ---- GEMM ----
    int og = tid & 15, rg = tid >> 4;     // 16 out groups, 8 row groups
    int o0 = og * 8, r0 = rg * 8;

    float acc[8][8];
    #pragma unroll
    for (int i = 0; i < 8; ++i)
        #pragma unroll
        for (int j = 0; j < 8; ++j) acc[i][j] = 0.f;

    #pragma unroll 8
    for (int k = 0; k < FK; ++k) {
        float a[8], b[8];
        float4 t;
        t = *(const float4*)(sIn + k * LDI2 + r0);     a[0]=t.x; a[1]=t.y; a[2]=t.z; a[3]=t.w;
        t = *(const float4*)(sIn + k * LDI2 + r0 + 4); a[4]=t.x; a[5]=t.y; a[6]=t.z; a[7]=t.w;
        t = *(const float4*)(sW  + k * D    + o0);     b[0]=t.x; b[1]=t.y; b[2]=t.z; b[3]=t.w;
        t = *(const float4*)(sW  + k * D    + o0 + 4); b[4]=t.x; b[5]=t.y; b[6]=t.z; b[7]=t.w;
        #pragma unroll
        for (int i = 0; i < 8; ++i)
            #pragma unroll
            for (int j = 0; j < 8; ++j)
                acc[i][j] = fmaf(a[i], b[j], acc[i][j]);
    }

    // ---- epilogue: +fc_b, relu, store ----
    float bv[8];
    #pragma unroll
    for (int j = 0; j < 8; ++j) bv[j] = fcb[o0 + j];

    #pragma unroll
    for (int i = 0; i < 8; ++i) {
        int row = rbase + r0 + i;
        if (row < N) {
            float4 w0, w1;
            w0.x = fmaxf(acc[i][0] + bv[0], 0.f);
            w0.y = fmaxf(acc[i][1] + bv[1], 0.f);
            w0.z = fmaxf(acc[i][2] + bv[2], 0.f);
            w0.w = fmaxf(acc[i][3] + bv[3], 0.f);
            w1.x = fmaxf(acc[i][4] + bv[4], 0.f);
            w1.y = fmaxf(acc[i][5] + bv[5], 0.f);
            w1.z = fmaxf(acc[i][6] + bv[6], 0.f);
            w1.w = fmaxf(acc[i][7] + bv[7], 0.f);
            *(float4*)(out + (size_t)row * D + o0)     = w0;
            *(float4*)(out + (size_t)row * D + o0 + 4) = w1;
        }
    }
}

// ---------------------------------------------------------------------------
// kernel_launch
// ---------------------------------------------------------------------------
extern "C" void kernel_launch(void* const* d_in, const int* in_sizes, int n_in,
                              void* d_out, int out_size) {
    const float* x         = (const float*)d_in[0];
    const float* rdf_feat  = (const float*)d_in[1];
    const float* bdf_feat  = (const float*)d_in[2];
    const int*   atom_idx  = (const int*)  d_in[3];
    const int*   ele_idx   = (const int*)  d_in[4];
    const float* rdf_W     = (const float*)d_in[5];
    const float* rdf_b     = (const float*)d_in[6];
    const float* rdf_gamma = (const float*)d_in[7];
    const float* rdf_beta  = (const float*)d_in[8];
    const float* bdf_W     = (const float*)d_in[9];
    const float* bdf_b     = (const float*)d_in[10];
    const float* bdf_gamma = (const float*)d_in[11];
    const float* bdf_beta  = (const float*)d_in[12];
    const float* fc_W      = (const float*)d_in[13];
    const float* fc_b      = (const float*)d_in[14];
    float*       out       = (float*)d_out;

    int N = in_sizes[3];               // atom_idx element count
    if (N > MAX_N) N = MAX_N;

    cudaFuncSetAttribute(layer_gemm_kernel,
                         cudaFuncAttributeMaxDynamicSharedMemorySize, SMEM_LAYER);
    cudaFuncSetAttribute(fc_gemm_kernel,
                         cudaFuncAttributeMaxDynamicSharedMemorySize, SMEM_FC);

    zero_kernel<<<1024, 256>>>();

    int segBlocks = (N + 63) / 64;
    segsum_kernel<<<segBlocks, 256>>>(x, atom_idx, ele_idx, N);

    finalize_kernel<<<1024, 256>>>();

    int gemmBlocks = (N + 127) / 128;
    layer_gemm_kernel<<<gemmBlocks, 256, SMEM_LAYER>>>(
        rdf_feat, atom_idx, ele_idx, rdf_W, rdf_b, 0, N);
    layer_gemm_kernel<<<gemmBlocks, 256, SMEM_LAYER>>>(
        bdf_feat, atom_idx, ele_idx, bdf_W, bdf_b, 1, N);

    bnparams_kernel<<<1, 128>>>(rdf_gamma, rdf_beta, bdf_gamma, bdf_beta,
                                1.0f / (float)N);

    int fcBlocks = (N + 63) / 64;
    fc_gemm_kernel<<<fcBlocks, 128, SMEM_FC>>>(x, fc_W, fc_b, out, N);
}

// round 4
// speedup vs baseline: 1.9147x; 1.9147x over previous
#include <cuda_runtime.h>
#include <cuda_bf16.h>
#include <cstdint>

// ---------------------------------------------------------------------------
// ModuleDistLayers — tensor-core (bf16 2-term split mma.sync) pipeline.
//
//   K0 zero      : clear segment accumulators + BN stats
//   K1 segsum    : read x once; run-length atomics for sorted atom_idx,
//                  red.global.v4 atomics for random ele_idx
//   K2 finalize  : pa = relu(atom_sum/max(cnt,1)), pe likewise  (fp32)
//   K3 layer x2  : h = W @ [feat|pa|pe] + b via m16n8k16 bf16 split MMA
//                  (128x128 CTA tile, K=192 single-stage) + BN stats
//   K4 bnparams  : per-feature scale/shift
//   K5 fc        : x1/x2 = relu(BN(h)+x); out = relu(fcW@[x1|x2]+fcb)
//                  (128x128 CTA tile, K=256 in two 128-staged halves)
// ---------------------------------------------------------------------------

#define N_GRAPHS 4096
#define N_ELE    16384
#define MAX_N    500000
#define D        128
#define NAE      64

// ---------------- device-global scratch -----------------------------------
__device__ float g_atom_sum[N_GRAPHS * NAE];
__device__ float g_atom_cnt[N_GRAPHS];
__device__ float g_ele_sum[N_ELE * NAE];
__device__ float g_ele_cnt[N_ELE];
__device__ float g_pa[N_GRAPHS * NAE];
__device__ float g_pe[N_ELE * NAE];
__device__ float g_h1[(size_t)MAX_N * D];
__device__ float g_h2[(size_t)MAX_N * D];
__device__ float g_stats[4 * D];            // sum1, sq1, sum2, sq2
__device__ float g_bn[4 * D];               // scale1, shift1, scale2, shift2

// ---------------- helpers --------------------------------------------------
__device__ __forceinline__ void bsplit(float x, __nv_bfloat16& h, __nv_bfloat16& l) {
    h = __float2bfloat16(x);
    l = __float2bfloat16(x - __bfloat162float(h));
}

__device__ __forceinline__ void mma16816(float* c,
                                         uint32_t a0, uint32_t a1, uint32_t a2, uint32_t a3,
                                         uint32_t b0, uint32_t b1) {
    asm volatile(
        "mma.sync.aligned.m16n8k16.row.col.f32.bf16.bf16.f32 "
        "{%0,%1,%2,%3}, {%4,%5,%6,%7}, {%8,%9}, {%0,%1,%2,%3};\n"
        : "+f"(c[0]), "+f"(c[1]), "+f"(c[2]), "+f"(c[3])
        : "r"(a0), "r"(a1), "r"(a2), "r"(a3), "r"(b0), "r"(b1));
}

__device__ __forceinline__ void red_v4(float* addr, float4 v) {
    asm volatile("red.global.add.v4.f32 [%0], {%1,%2,%3,%4};"
                 :: "l"(addr), "f"(v.x), "f"(v.y), "f"(v.z), "f"(v.w) : "memory");
}

// ---------------------------------------------------------------------------
// K0: zero accumulators
// ---------------------------------------------------------------------------
__global__ void zero_kernel() {
    int i  = blockIdx.x * blockDim.x + threadIdx.x;
    int gs = gridDim.x * blockDim.x;
    for (int j = i; j < N_GRAPHS * NAE; j += gs) g_atom_sum[j] = 0.f;
    for (int j = i; j < N_ELE * NAE;    j += gs) g_ele_sum[j]  = 0.f;
    for (int j = i; j < N_GRAPHS;       j += gs) g_atom_cnt[j] = 0.f;
    for (int j = i; j < N_ELE;          j += gs) g_ele_cnt[j]  = 0.f;
    for (int j = i; j < 4 * D;          j += gs) g_stats[j]    = 0.f;
}

// ---------------------------------------------------------------------------
// K1: segment sums.  Thread (cg, sg): 4 consecutive cols of 4 consecutive rows.
// atom_idx sorted -> run-length aggregation; ele via red.v4.
// ---------------------------------------------------------------------------
__global__ void segsum_kernel(const float* __restrict__ x,
                              const int*   __restrict__ aidx,
                              const int*   __restrict__ eidx,
                              int N) {
    int tid = threadIdx.x;            // 256
    int cg  = tid & 15;               // 4-col group: cols cg*4..cg*4+3
    int sg  = tid >> 4;               // 16 row streams
    int r0  = blockIdx.x * 64 + sg * 4;

    int    cur = -1;
    float4 acc = make_float4(0.f, 0.f, 0.f, 0.f);
    float  cnt = 0.f;

    #pragma unroll
    for (int t = 0; t < 4; ++t) {
        int row = r0 + t;
        if (row < N) {
            int a = aidx[row];
            float4 va = *(const float4*)(x + (size_t)row * D + cg * 4);
            float4 ve = *(const float4*)(x + (size_t)row * D + NAE + cg * 4);
            if (a != cur) {
                if (cur >= 0) {
                    red_v4(&g_atom_sum[cur * NAE + cg * 4], acc);
                    if (cg == 0) atomicAdd(&g_atom_cnt[cur], cnt);
                }
                cur = a; acc = va; cnt = 1.f;
            } else {
                acc.x += va.x; acc.y += va.y; acc.z += va.z; acc.w += va.w;
                cnt += 1.f;
            }
            int e = eidx[row];
            red_v4(&g_ele_sum[e * NAE + cg * 4], ve);
            if (cg == 0) atomicAdd(&g_ele_cnt[e], 1.f);
        }
    }
    if (cur >= 0) {
        red_v4(&g_atom_sum[cur * NAE + cg * 4], acc);
        if (cg == 0) atomicAdd(&g_atom_cnt[cur], cnt);
    }
}

// ---------------------------------------------------------------------------
// K2: pa = relu(sum / max(cnt,1)), pe likewise (fp32; split happens per-tile)
// ---------------------------------------------------------------------------
__global__ void finalize_kernel() {
    int i  = blockIdx.x * blockDim.x + threadIdx.x;
    int gs = gridDim.x * blockDim.x;
    for (int j = i; j < N_GRAPHS * NAE; j += gs) {
        float m = g_atom_sum[j] / fmaxf(g_atom_cnt[j >> 6], 1.f);
        g_pa[j] = fmaxf(m, 0.f);
    }
    for (int j = i; j < N_ELE * NAE; j += gs) {
        float m = g_ele_sum[j] / fmaxf(g_ele_cnt[j >> 6], 1.f);
        g_pe[j] = fmaxf(m, 0.f);
    }
}

// ---------------------------------------------------------------------------
// K3: layer GEMM via bf16-split mma.  CTA 128 rows x 128 outs, K=192.
// smem: sAhi/sAlo [128][SA], sWhi/sWlo [128][SA]  (SA=200 -> conflict-free)
// 8 warps in 2(M) x 4(N) grid, warp tile 64x32, frag tile m16n8k16.
// ---------------------------------------------------------------------------
#define SA 200
#define SMEM_LAYER (4 * 128 * SA * 2)     // 204,800 B

__global__ __launch_bounds__(256, 1)
void layer_gemm_kernel(const float* __restrict__ feat,   // [N][64]
                       const int*   __restrict__ aidx,
                       const int*   __restrict__ eidx,
                       const float* __restrict__ W,      // [128][192]
                       const float* __restrict__ bias,   // [128]
                       int layer, int N) {
    extern __shared__ __nv_bfloat16 smB[];
    __nv_bfloat16* sAhi = smB;
    __nv_bfloat16* sAlo = smB + 128 * SA;
    __nv_bfloat16* sWhi = smB + 2 * 128 * SA;
    __nv_bfloat16* sWlo = smB + 3 * 128 * SA;
    __shared__ float sSum[D];
    __shared__ float sSq[D];
    __shared__ int   sAi[128];
    __shared__ int   sEi[128];

    int tid   = threadIdx.x;
    int rbase = blockIdx.x * 128;

    // ---- W -> smem (split) ----
    {
        int o = tid & 127, half = tid >> 7;
        const float4* src = (const float4*)(W + (size_t)o * 192) + half * 24;
        #pragma unroll
        for (int j = 0; j < 24; ++j) {
            float4 v = src[j];
            int k = half * 96 + j * 4;
            bsplit(v.x, sWhi[o * SA + k + 0], sWlo[o * SA + k + 0]);
            bsplit(v.y, sWhi[o * SA + k + 1], sWlo[o * SA + k + 1]);
            bsplit(v.z, sWhi[o * SA + k + 2], sWlo[o * SA + k + 2]);
            bsplit(v.w, sWhi[o * SA + k + 3], sWlo[o * SA + k + 3]);
        }
    }
    if (tid < 128) {
        int r = rbase + tid;
        sAi[tid] = (r < N) ? aidx[r] : 0;
        sEi[tid] = (r < N) ? eidx[r] : 0;
        sSum[tid] = 0.f;
        sSq[tid]  = 0.f;
    }
    __syncthreads();

    // ---- input tile [feat|pa|pe] -> smem (split) ----
    {
        int c = tid & 63, rr = tid >> 6;
        for (int r = rr; r < 128; r += 4) {
            int row = rbase + r;
            float f = 0.f, pav = 0.f, pev = 0.f;
            if (row < N) {
                f   = feat[(size_t)row * NAE + c];
                pav = g_pa[sAi[r] * NAE + c];
                pev = g_pe[sEi[r] * NAE + c];
            }
            bsplit(f,   sAhi[r * SA + c],        sAlo[r * SA + c]);
            bsplit(pav, sAhi[r * SA + 64 + c],   sAlo[r * SA + 64 + c]);
            bsplit(pev, sAhi[r * SA + 128 + c],  sAlo[r * SA + 128 + c]);
        }
    }
    __syncthreads();

    // ---- MMA main loop ----
    int warp  = tid >> 5, lane = tid & 31;
    int warpM = (warp >> 2) * 64;      // 0 or 64
    int warpN = (warp & 3) * 32;       // 0,32,64,96
    int gr = lane >> 2, tig = lane & 3;

    float acc[4][4][4];
    #pragma unroll
    for (int mi = 0; mi < 4; ++mi)
        #pragma unroll
        for (int ni = 0; ni < 4; ++ni)
            #pragma unroll
            for (int q = 0; q < 4; ++q) acc[mi][ni][q] = 0.f;

    for (int kk = 0; kk < 12; ++kk) {
        uint32_t Ah[4][4], Al[4][4], Bh[4][2], Bl[4][2];
        #pragma unroll
        for (int mi = 0; mi < 4; ++mi) {
            int off = (warpM + mi * 16 + gr) * SA + kk * 16 + tig * 2;
            Ah[mi][0] = *(const uint32_t*)(sAhi + off);
            Ah[mi][1] = *(const uint32_t*)(sAhi + off + 8 * SA);
            Ah[mi][2] = *(const uint32_t*)(sAhi + off + 8);
            Ah[mi][3] = *(const uint32_t*)(sAhi + off + 8 * SA + 8);
            Al[mi][0] = *(const uint32_t*)(sAlo + off);
            Al[mi][1] = *(const uint32_t*)(sAlo + off + 8 * SA);
            Al[mi][2] = *(const uint32_t*)(sAlo + off + 8);
            Al[mi][3] = *(const uint32_t*)(sAlo + off + 8 * SA + 8);
        }
        #pragma unroll
        for (int ni = 0; ni < 4; ++ni) {
            int off = (warpN + ni * 8 + gr) * SA + kk * 16 + tig * 2;
            Bh[ni][0] = *(const uint32_t*)(sWhi + off);
            Bh[ni][1] = *(const uint32_t*)(sWhi + off + 8);
            Bl[ni][0] = *(const uint32_t*)(sWlo + off);
            Bl[ni][1] = *(const uint32_t*)(sWlo + off + 8);
        }
        #pragma unroll
        for (int mi = 0; mi < 4; ++mi)
            #pragma unroll
            for (int ni = 0; ni < 4; ++ni) {
                mma16816(acc[mi][ni], Ah[mi][0], Ah[mi][1], Ah[mi][2], Ah[mi][3],
                         Bh[ni][0], Bh[ni][1]);
                mma16816(acc[mi][ni], Ah[mi][0], Ah[mi][1], Ah[mi][2], Ah[mi][3],
                         Bl[ni][0], Bl[ni][1]);
                mma16816(acc[mi][ni], Al[mi][0], Al[mi][1], Al[mi][2], Al[mi][3],
                         Bh[ni][0], Bh[ni][1]);
            }
    }

    // ---- epilogue: +bias, write h, accumulate BN stats ----
    float* h_out = (layer == 0) ? g_h1 : g_h2;
    #pragma unroll
    for (int ni = 0; ni < 4; ++ni) {
        int col = warpN + ni * 8 + tig * 2;
        float b0 = bias[col], b1 = bias[col + 1];
        float ps0 = 0.f, ps1 = 0.f, pq0 = 0.f, pq1 = 0.f;
        #pragma unroll
        for (int mi = 0; mi < 4; ++mi) {
            int r0 = rbase + warpM + mi * 16 + gr;
            float v0 = acc[mi][ni][0] + b0;
            float v1 = acc[mi][ni][1] + b1;
            if (r0 < N) {
                *(float2*)(h_out + (size_t)r0 * D + col) = make_float2(v0, v1);
                ps0 += v0; ps1 += v1; pq0 += v0 * v0; pq1 += v1 * v1;
            }
            int r1 = r0 + 8;
            float v2 = acc[mi][ni][2] + b0;
            float v3 = acc[mi][ni][3] + b1;
            if (r1 < N) {
                *(float2*)(h_out + (size_t)r1 * D + col) = make_float2(v2, v3);
                ps0 += v2; ps1 += v3; pq0 += v2 * v2; pq1 += v3 * v3;
            }
        }
        #pragma unroll
        for (int s = 4; s <= 16; s <<= 1) {
            ps0 += __shfl_xor_sync(0xffffffffu, ps0, s);
            ps1 += __shfl_xor_sync(0xffffffffu, ps1, s);
            pq0 += __shfl_xor_sync(0xffffffffu, pq0, s);
            pq1 += __shfl_xor_sync(0xffffffffu, pq1, s);
        }
        if (gr == 0) {
            atomicAdd(&sSum[col],     ps0);
            atomicAdd(&sSum[col + 1], ps1);
            atomicAdd(&sSq[col],      pq0);
            atomicAdd(&sSq[col + 1],  pq1);
        }
    }
    __syncthreads();
    if (tid < 128) {
        float* st = g_stats + layer * (2 * D);
        atomicAdd(&st[tid],     sSum[tid]);
        atomicAdd(&st[D + tid], sSq[tid]);
    }
}

// ---------------------------------------------------------------------------
// K4: BN scale/shift per feature
// ---------------------------------------------------------------------------
__global__ void bnparams_kernel(const float* __restrict__ g1, const float* __restrict__ b1,
                                const float* __restrict__ g2, const float* __restrict__ b2,
                                float invN) {
    int o = threadIdx.x;   // 128
    float m  = g_stats[o] * invN;
    float v  = fmaxf(g_stats[D + o] * invN - m * m, 0.f);
    float sc = g1[o] * rsqrtf(v + 1e-5f);
    g_bn[o]       = sc;
    g_bn[D + o]   = b1[o] - m * sc;

    m  = g_stats[2 * D + o] * invN;
    v  = fmaxf(g_stats[3 * D + o] * invN - m * m, 0.f);
    sc = g2[o] * rsqrtf(v + 1e-5f);
    g_bn[2 * D + o] = sc;
    g_bn[3 * D + o] = b2[o] - m * sc;
}

// ---------------------------------------------------------------------------
// K5: BN + residual + relu + fc GEMM.  CTA 128 rows x 128 outs, K=256 staged
// as two K=128 halves (stage 0 = x1 from h1, stage 1 = x2 from h2).
// ---------------------------------------------------------------------------
#define SA2 136
#define SMEM_FC (4 * 128 * SA2 * 2)    // 139,264 B

__global__ __launch_bounds__(256, 1)
void fc_gemm_kernel(const float* __restrict__ x,     // [N][128]
                    const float* __restrict__ fcW,   // [128][256]
                    const float* __restrict__ fcb,   // [128]
                    float* __restrict__ out, int N) {
    extern __shared__ __nv_bfloat16 smB[];
    __nv_bfloat16* sAhi = smB;
    __nv_bfloat16* sAlo = smB + 128 * SA2;
    __nv_bfloat16* sWhi = smB + 2 * 128 * SA2;
    __nv_bfloat16* sWlo = smB + 3 * 128 * SA2;

    int tid   = threadIdx.x;
    int rbase = blockIdx.x * 128;

    int warp  = tid >> 5, lane = tid & 31;
    int warpM = (warp >> 2) * 64;
    int warpN = (warp & 3) * 32;
    int gr = lane >> 2, tig = lane & 3;

    float acc[4][4][4];
    #pragma unroll
    for (int mi = 0; mi < 4; ++mi)
        #pragma unroll
        for (int ni = 0; ni < 4; ++ni)
            #pragma unroll
            for (int q = 0; q < 4; ++q) acc[mi][ni][q] = 0.f;

    for (int ks = 0; ks < 2; ++ks) {
        // ---- fill W half ----
        {
            int o = tid & 127, half = tid >> 7;
            const float4* src = (const float4*)(fcW + (size_t)o * 256 + ks * 128) + half * 16;
            #pragma unroll
            for (int j = 0; j < 16; ++j) {
                float4 v = src[j];
                int k = half * 64 + j * 4;
                bsplit(v.x, sWhi[o * SA2 + k + 0], sWlo[o * SA2 + k + 0]);
                bsplit(v.y, sWhi[o * SA2 + k + 1], sWlo[o * SA2 + k + 1]);
                bsplit(v.z, sWhi[o * SA2 + k + 2], sWlo[o * SA2 + k + 2]);
                bsplit(v.w, sWhi[o * SA2 + k + 3], sWlo[o * SA2 + k + 3]);
            }
        }
        // ---- fill A half: relu(BN(h) + x) ----
        {
            const float* h = (ks == 0) ? g_h1 : g_h2;
            int c  = tid & 127, rr = tid >> 7;
            float sc = g_bn[2 * D * ks + c];
            float sh = g_bn[2 * D * ks + D + c];
            for (int r = rr; r < 128; r += 2) {
                int row = rbase + r;
                float v = 0.f;
                if (row < N) {
                    float xv = x[(size_t)row * D + c];
                    v = fmaxf(fmaf(h[(size_t)row * D + c], sc, sh) + xv, 0.f);
                }
                bsplit(v, sAhi[r * SA2 + c], sAlo[r * SA2 + c]);
            }
        }
        __syncthreads();

        // ---- MMA over this K half ----
        for (int kk = 0; kk < 8; ++kk) {
            uint32_t Ah[4][4], Al[4][4], Bh[4][2], Bl[4][2];
            #pragma unroll
            for (int mi = 0; mi < 4; ++mi) {
                int off = (warpM + mi * 16 + gr) * SA2 + kk * 16 + tig * 2;
                Ah[mi][0] = *(const uint32_t*)(sAhi + off);
                Ah[mi][1] = *(const uint32_t*)(sAhi + off + 8 * SA2);
                Ah[mi][2] = *(const uint32_t*)(sAhi + off + 8);
                Ah[mi][3] = *(const uint32_t*)(sAhi + off + 8 * SA2 + 8);
                Al[mi][0] = *(const uint32_t*)(sAlo + off);
                Al[mi][1] = *(const uint32_t*)(sAlo + off + 8 * SA2);
                Al[mi][2] = *(const uint32_t*)(sAlo + off + 8);
                Al[mi][3] = *(const uint32_t*)(sAlo + off + 8 * SA2 + 8);
            }
            #pragma unroll
            for (int ni = 0; ni < 4; ++ni) {
                int off = (warpN + ni * 8 + gr) * SA2 + kk * 16 + tig * 2;
                Bh[ni][0] = *(const uint32_t*)(sWhi + off);
                Bh[ni][1] = *(const uint32_t*)(sWhi + off + 8);
                Bl[ni][0] = *(const uint32_t*)(sWlo + off);
                Bl[ni][1] = *(const uint32_t*)(sWlo + off + 8);
            }
            #pragma unroll
            for (int mi = 0; mi < 4; ++mi)
                #pragma unroll
                for (int ni = 0; ni < 4; ++ni) {
                    mma16816(acc[mi][ni], Ah[mi][0], Ah[mi][1], Ah[mi][2], Ah[mi][3],
                             Bh[ni][0], Bh[ni][1]);
                    mma16816(acc[mi][ni], Ah[mi][0], Ah[mi][1], Ah[mi][2], Ah[mi][3],
                             Bl[ni][0], Bl[ni][1]);
                    mma16816(acc[mi][ni], Al[mi][0], Al[mi][1], Al[mi][2], Al[mi][3],
                             Bh[ni][0], Bh[ni][1]);
                }
        }
        __syncthreads();
    }

    // ---- epilogue: +fcb, relu, store ----
    #pragma unroll
    for (int ni = 0; ni < 4; ++ni) {
        int col = warpN + ni * 8 + tig * 2;
        float b0 = fcb[col], b1 = fcb[col + 1];
        #pragma unroll
        for (int mi = 0; mi < 4; ++mi) {
            int r0 = rbase + warpM + mi * 16 + gr;
            if (r0 < N) {
                *(float2*)(out + (size_t)r0 * D + col) =
                    make_float2(fmaxf(acc[mi][ni][0] + b0, 0.f),
                                fmaxf(acc[mi][ni][1] + b1, 0.f));
            }
            int r1 = r0 + 8;
            if (r1 < N) {
                *(float2*)(out + (size_t)r1 * D + col) =
                    make_float2(fmaxf(acc[mi][ni][2] + b0, 0.f),
                                fmaxf(acc[mi][ni][3] + b1, 0.f));
            }
        }
    }
}

// ---------------------------------------------------------------------------
// kernel_launch
// ---------------------------------------------------------------------------
extern "C" void kernel_launch(void* const* d_in, const int* in_sizes, int n_in,
                              void* d_out, int out_size) {
    const float* x         = (const float*)d_in[0];
    const float* rdf_feat  = (const float*)d_in[1];
    const float* bdf_feat  = (const float*)d_in[2];
    const int*   atom_idx  = (const int*)  d_in[3];
    const int*   ele_idx   = (const int*)  d_in[4];
    const float* rdf_W     = (const float*)d_in[5];
    const float* rdf_b     = (const float*)d_in[6];
    const float* rdf_gamma = (const float*)d_in[7];
    const float* rdf_beta  = (const float*)d_in[8];
    const float* bdf_W     = (const float*)d_in[9];
    const float* bdf_b     = (const float*)d_in[10];
    const float* bdf_gamma = (const float*)d_in[11];
    const float* bdf_beta  = (const float*)d_in[12];
    const float* fc_W      = (const float*)d_in[13];
    const float* fc_b      = (const float*)d_in[14];
    float*       out       = (float*)d_out;

    int N = in_sizes[3];
    if (N > MAX_N) N = MAX_N;

    cudaFuncSetAttribute(layer_gemm_kernel,
                         cudaFuncAttributeMaxDynamicSharedMemorySize, SMEM_LAYER);
    cudaFuncSetAttribute(fc_gemm_kernel,
                         cudaFuncAttributeMaxDynamicSharedMemorySize, SMEM_FC);

    zero_kernel<<<1024, 256>>>();

    int segBlocks = (N + 63) / 64;
    segsum_kernel<<<segBlocks, 256>>>(x, atom_idx, ele_idx, N);

    finalize_kernel<<<1024, 256>>>();

    int gemmBlocks = (N + 127) / 128;
    layer_gemm_kernel<<<gemmBlocks, 256, SMEM_LAYER>>>(
        rdf_feat, atom_idx, ele_idx, rdf_W, rdf_b, 0, N);
    layer_gemm_kernel<<<gemmBlocks, 256, SMEM_LAYER>>>(
        bdf_feat, atom_idx, ele_idx, bdf_W, bdf_b, 1, N);

    bnparams_kernel<<<1, 128>>>(rdf_gamma, rdf_beta, bdf_gamma, bdf_beta,
                                1.0f / (float)N);

    fc_gemm_kernel<<<gemmBlocks, 256, SMEM_FC>>>(x, fc_W, fc_b, out, N);
}